// round 6
// baseline (speedup 1.0000x reference)
#include <cuda_runtime.h>
#include <cuda_bf16.h>

#define NMAX 100000
#define DIM  256
#define NEG_SLOPE 0.01f

// -------------------- scratch (device globals) --------------------
__device__ float BUF_B[(size_t)NMAX * DIM];  // h_lin / h2_lin (gemm outputs)
__device__ float BUF_C[(size_t)NMAX * DIM];  // agg1
__device__ float BUF_D[(size_t)NMAX * DIM];  // agg2
__device__ float WHI[5 * 65536];             // tf32-hi of W1, W2top, W2bot, Wltop, Wlbot
__device__ float WLO[5 * 65536];             // residual lo
__device__ float RA2[128 * DIM];             // leaky(features[root])
__device__ float RA3[128 * DIM];             // h1[root] = agg1[root]+b1
__device__ float RC2[128 * DIM];             // RA2 @ W2bot
__device__ float RC3[128 * DIM];             // RA3 @ Wlbot

__device__ __forceinline__ float leaky1(float v) { return v >= 0.0f ? v : NEG_SLOPE * v; }
__device__ __forceinline__ float4 leaky4(float4 v) {
    v.x = leaky1(v.x); v.y = leaky1(v.y); v.z = leaky1(v.z); v.w = leaky1(v.w);
    return v;
}
__device__ __forceinline__ float tf32r(float x) {
    float r; asm("cvt.rna.tf32.f32 %0, %1;" : "=f"(r) : "f"(x)); return r;
}

// -------------------- weight decomposition --------------------
__global__ void decompose_w(const float* __restrict__ W1, const float* __restrict__ W2,
                            const float* __restrict__ Wl) {
    int slot = blockIdx.y;
    int idx = blockIdx.x * 256 + threadIdx.x;
    const float* src;
    if (slot == 0) src = W1;
    else if (slot == 1) src = W2;
    else if (slot == 2) src = W2 + 65536;
    else if (slot == 3) src = Wl;
    else src = Wl + 65536;
    float v = src[idx];
    float hi = tf32r(v);
    WHI[slot * 65536 + idx] = hi;
    WLO[slot * 65536 + idx] = tf32r(v - hi);
}

// -------------------- tf32 tensor-core GEMM, fragment-permuted smem ---------
// C[nrows,256] = op(A)[nrows,256] @ B[256,256]; op = leaky(x + abias) if abias.
// 3-pass split: Ahi*Bhi + Ahi*Blo + Alo*Bhi.
// Epilogue: +bias, +rc[batch[row]], optional leaky.
// 256 threads = 8 warps (2m x 4n), tile 128x128, chunk K=16.
__device__ __forceinline__ void mma8(float* c, const float* a, const float* b) {
    asm volatile(
        "mma.sync.aligned.m16n8k8.row.col.f32.tf32.tf32.f32 "
        "{%0,%1,%2,%3}, {%4,%5,%6,%7}, {%8,%9}, {%0,%1,%2,%3};"
        : "+f"(c[0]), "+f"(c[1]), "+f"(c[2]), "+f"(c[3])
        : "r"(__float_as_uint(a[0])), "r"(__float_as_uint(a[1])),
          "r"(__float_as_uint(a[2])), "r"(__float_as_uint(a[3])),
          "r"(__float_as_uint(b[0])), "r"(__float_as_uint(b[1])));
}

__global__ void __launch_bounds__(256) gemm_tf32(
    const float* __restrict__ A, const float* __restrict__ BH, const float* __restrict__ BL,
    float* __restrict__ C, const float* __restrict__ bias,
    const float* __restrict__ rc, const int* __restrict__ batch,
    const float* __restrict__ abias,
    int nrows, int leakyFlag)
{
    // fragment-permuted tiles: A[mtg 0..7][ks 0..1][lane 0..31][reg 0..3]
    //                          B[ntg 0..15][ks 0..1][lane 0..31][reg 0..1]
    __shared__ float As_hi[2048];
    __shared__ float As_lo[2048];
    __shared__ float Bs_hi[2048];
    __shared__ float Bs_lo[2048];

    const int tid = threadIdx.x;
    const int warp = tid >> 5, lane = tid & 31;
    const int wm = (warp & 1) * 64;         // 0 / 64
    const int wn = (warp >> 1) * 32;        // 0,32,64,96
    const int g = lane >> 2, t = lane & 3;
    const int row0 = blockIdx.x * 128;
    const int col0 = blockIdx.y * 128;

    float acc[4][4][4];
    #pragma unroll
    for (int mt = 0; mt < 4; mt++)
        #pragma unroll
        for (int nt = 0; nt < 4; nt++)
            #pragma unroll
            for (int i = 0; i < 4; i++) acc[mt][nt][i] = 0.0f;

    // staging thread coordinates (2 float4 per thread for each of A,B)
    const int ar_[2]  = { tid >> 2, (tid + 256) >> 2 };          // A row 0..127
    const int ac4 = (tid & 3) * 4;                               // A col group
    const int aks = ac4 >> 3, arh = (ac4 >> 2) & 1;              // ks, rhalf (same for 2 frags)
    const int kr_[2]  = { tid >> 5, (tid + 256) >> 5 };          // B k-row 0..15
    const int bc = (tid & 31) * 4;                               // B col group

    float4 ra[2], rbh[2], rbl[2];

    // prefetch chunk 0
    #pragma unroll
    for (int i = 0; i < 2; i++) {
        int gr = row0 + ar_[i];
        ra[i] = (gr < nrows) ? *(const float4*)(A + (long long)gr * 256 + ac4)
                             : make_float4(0.f, 0.f, 0.f, 0.f);
        rbh[i] = *(const float4*)(BH + (long long)kr_[i] * 256 + col0 + bc);
        rbl[i] = *(const float4*)(BL + (long long)kr_[i] * 256 + col0 + bc);
    }

    for (int ch = 0; ch < 16; ch++) {
        int k0 = ch * 16;
        __syncthreads();
        // ---- stage A (transform + hi/lo split, permuted) ----
        #pragma unroll
        for (int i = 0; i < 2; i++) {
            float4 v = ra[i];
            if (abias) {
                float4 ab = *(const float4*)(abias + k0 + ac4);
                v.x += ab.x; v.y += ab.y; v.z += ab.z; v.w += ab.w;
                v = leaky4(v);
            }
            int r_ = ar_[i];
            int mtg = r_ >> 4;
            int row16 = r_ & 15;
            int gg = row16 & 7, mh = row16 >> 3;
            int reg = mh + 2 * arh;
            int base = ((mtg * 2 + aks) * 32 + gg * 4) * 4 + reg;
            float h0 = tf32r(v.x), h1v = tf32r(v.y), h2 = tf32r(v.z), h3 = tf32r(v.w);
            As_hi[base + 0]  = h0;  As_lo[base + 0]  = tf32r(v.x - h0);
            As_hi[base + 4]  = h1v; As_lo[base + 4]  = tf32r(v.y - h1v);
            As_hi[base + 8]  = h2;  As_lo[base + 8]  = tf32r(v.z - h2);
            As_hi[base + 12] = h3;  As_lo[base + 12] = tf32r(v.w - h3);
        }
        // ---- stage B (permuted) ----
        #pragma unroll
        for (int i = 0; i < 2; i++) {
            int kr = kr_[i];
            int ks2 = kr >> 3, t2 = kr & 3, r2 = (kr >> 2) & 1;
            const float* ph = (const float*)&rbh[i];
            const float* pl = (const float*)&rbl[i];
            #pragma unroll
            for (int j = 0; j < 4; j++) {
                int c = bc + j;
                int ntg = c >> 3, g2 = c & 7;
                int idx = ((ntg * 2 + ks2) * 32 + g2 * 4 + t2) * 2 + r2;
                Bs_hi[idx] = ph[j];
                Bs_lo[idx] = pl[j];
            }
        }
        __syncthreads();

        // ---- prefetch next chunk ----
        if (ch < 15) {
            int kn = k0 + 16;
            #pragma unroll
            for (int i = 0; i < 2; i++) {
                int gr = row0 + ar_[i];
                ra[i] = (gr < nrows) ? *(const float4*)(A + (long long)gr * 256 + kn + ac4)
                                     : make_float4(0.f, 0.f, 0.f, 0.f);
                rbh[i] = *(const float4*)(BH + (long long)(kn + kr_[i]) * 256 + col0 + bc);
                rbl[i] = *(const float4*)(BL + (long long)(kn + kr_[i]) * 256 + col0 + bc);
            }
        }

        // ---- compute ----
        #pragma unroll
        for (int ks = 0; ks < 2; ks++) {
            float4 ah[4], al[4];
            #pragma unroll
            for (int mt = 0; mt < 4; mt++) {
                int mtg = (wm >> 4) + mt;
                int off = ((mtg * 2 + ks) * 32 + lane) * 4;
                ah[mt] = *(const float4*)&As_hi[off];
                al[mt] = *(const float4*)&As_lo[off];
            }
            float2 bh[4], bl2[4];
            #pragma unroll
            for (int nt = 0; nt < 4; nt++) {
                int ntg = (wn >> 3) + nt;
                int off = ((ntg * 2 + ks) * 32 + lane) * 2;
                bh[nt]  = *(const float2*)&Bs_hi[off];
                bl2[nt] = *(const float2*)&Bs_lo[off];
            }
            #pragma unroll
            for (int mt = 0; mt < 4; mt++)
                #pragma unroll
                for (int nt = 0; nt < 4; nt++) {
                    mma8(acc[mt][nt], (const float*)&ah[mt], (const float*)&bh[nt]);
                    mma8(acc[mt][nt], (const float*)&ah[mt], (const float*)&bl2[nt]);
                    mma8(acc[mt][nt], (const float*)&al[mt], (const float*)&bh[nt]);
                }
        }
    }

    // ---- epilogue ----
    #pragma unroll
    for (int mt = 0; mt < 4; mt++) {
        int r_lo = row0 + wm + mt * 16 + g;
        #pragma unroll
        for (int h = 0; h < 2; h++) {
            int gr = r_lo + 8 * h;
            if (gr >= nrows) continue;
            const float* rcrow = rc ? rc + (long long)batch[gr] * 256 : nullptr;
            #pragma unroll
            for (int nt = 0; nt < 4; nt++) {
                int gc = col0 + wn + nt * 8 + 2 * t;
                float vx = acc[mt][nt][h * 2 + 0];
                float vy = acc[mt][nt][h * 2 + 1];
                if (bias) { float2 bb = *(const float2*)(bias + gc); vx += bb.x; vy += bb.y; }
                if (rcrow) { float2 rr = *(const float2*)(rcrow + gc); vx += rr.x; vy += rr.y; }
                if (leakyFlag) { vx = leaky1(vx); vy = leaky1(vy); }
                float2 o; o.x = vx; o.y = vy;
                *(float2*)(C + (long long)gr * 256 + gc) = o;
            }
        }
    }
}

// -------------------- edge scatter: agg[dst] += w * h[src] --------------------
__global__ void __launch_bounds__(256) scatter_kernel(
    const float* __restrict__ h, float* __restrict__ agg,
    const int* __restrict__ src, const int* __restrict__ dst,
    const float* __restrict__ w, int E)
{
    int warp = (blockIdx.x * blockDim.x + threadIdx.x) >> 5;
    int lane = threadIdx.x & 31;
    if (warp >= E) return;
    int s = src[warp], d = dst[warp];
    float wt = w[warp];
    const float4* hrow = (const float4*)(h + (long long)s * DIM);
    float* arow = agg + (long long)d * DIM;
    #pragma unroll
    for (int i = 0; i < 2; i++) {
        int gidx = lane + 32 * i;
        float4 v = __ldg(hrow + gidx);
        float* p = arow + gidx * 4;
        asm volatile("red.global.add.v4.f32 [%0], {%1,%2,%3,%4};"
                     :: "l"(p), "f"(wt * v.x), "f"(wt * v.y), "f"(wt * v.z), "f"(wt * v.w)
                     : "memory");
    }
}

// -------------------- small helpers --------------------
__global__ void zero2_kernel(float4* __restrict__ p, float4* __restrict__ q, long long n4) {
    long long i = (long long)blockIdx.x * blockDim.x + threadIdx.x;
    if (i < n4) {
        p[i] = make_float4(0.f, 0.f, 0.f, 0.f);
        q[i] = make_float4(0.f, 0.f, 0.f, 0.f);
    }
}

// dst[b] = op(src[root_idx[b]]) ; op: +abias (optional), leaky (optional)
__global__ void __launch_bounds__(64) gather_root(
    const float* __restrict__ src, const int* __restrict__ root_idx,
    const float* __restrict__ abias,
    float* __restrict__ dst, int applyLeaky)
{
    int b = blockIdx.x, t = threadIdx.x;
    int r = root_idx[b];
    float4 v = ((const float4*)(src + (long long)r * DIM))[t];
    if (abias) {
        float4 ab = ((const float4*)abias)[t];
        v.x += ab.x; v.y += ab.y; v.z += ab.z; v.w += ab.w;
    }
    if (applyLeaky) v = leaky4(v);
    ((float4*)(dst + (long long)b * DIM))[t] = v;
}

// -------------------- launch --------------------
extern "C" void kernel_launch(void* const* d_in, const int* in_sizes, int n_in,
                              void* d_out, int out_size)
{
    const float* features = (const float*)d_in[0];
    const float* values   = (const float*)d_in[1];
    const float* W1       = (const float*)d_in[2];
    const float* b1       = (const float*)d_in[3];
    const float* W2       = (const float*)d_in[4];
    const float* b2       = (const float*)d_in[5];
    const float* Wl       = (const float*)d_in[6];
    const float* bl       = (const float*)d_in[7];
    const int*   adjs     = (const int*)d_in[8];
    const int*   batch    = (const int*)d_in[9];
    const int*   root_idx = (const int*)d_in[10];
    float* out = (float*)d_out;

    const int N = in_sizes[0] / DIM;
    const int E = in_sizes[1];
    const int B = in_sizes[10];
    const int* src = adjs;
    const int* dst = adjs + E;

    float *bufB, *bufC, *bufD, *whi, *wlo, *ra2, *ra3, *rc2, *rc3;
    cudaGetSymbolAddress((void**)&bufB, BUF_B);
    cudaGetSymbolAddress((void**)&bufC, BUF_C);
    cudaGetSymbolAddress((void**)&bufD, BUF_D);
    cudaGetSymbolAddress((void**)&whi, WHI);
    cudaGetSymbolAddress((void**)&wlo, WLO);
    cudaGetSymbolAddress((void**)&ra2, RA2);
    cudaGetSymbolAddress((void**)&ra3, RA3);
    cudaGetSymbolAddress((void**)&rc2, RC2);
    cudaGetSymbolAddress((void**)&rc3, RC3);

    dim3 gemmGrid((N + 127) / 128, 2);
    dim3 tinyGrid((B + 127) / 128, 2);
    int scatterBlocks = (E + 7) / 8;
    long long n4 = (long long)N * DIM / 4;
    int zeroBlocks = (int)((n4 + 255) / 256);

    // 1. decompose weights; zero both agg buffers
    decompose_w<<<dim3(256, 5), 256>>>(W1, W2, Wl);
    zero2_kernel<<<zeroBlocks, 256>>>((float4*)bufC, (float4*)bufD, n4);
    // 2. rc2 = leaky(features[root]) @ W2bot
    gather_root<<<B, 64>>>(features, root_idx, nullptr, ra2, 1);
    gemm_tf32<<<tinyGrid, 256>>>(ra2, whi + 2 * 65536, wlo + 2 * 65536, rc2,
                                 nullptr, nullptr, nullptr, nullptr, B, 0);
    // 3. h_lin = features @ W1
    gemm_tf32<<<gemmGrid, 256>>>(features, whi, wlo, bufB,
                                 nullptr, nullptr, nullptr, nullptr, N, 0);
    // 4. agg1[dst] += v * h_lin[src]
    scatter_kernel<<<scatterBlocks, 256>>>(bufB, bufC, src, dst, values, E);
    // 5. rc3 = (agg1[root] + b1) @ Wlbot
    gather_root<<<B, 64>>>(bufC, root_idx, b1, ra3, 0);
    gemm_tf32<<<tinyGrid, 256>>>(ra3, whi + 4 * 65536, wlo + 4 * 65536, rc3,
                                 nullptr, nullptr, nullptr, nullptr, B, 0);
    // 6. h2_lin = leaky(agg1 + b1) @ W2top + rc2[batch]   (A-transform fused)
    gemm_tf32<<<gemmGrid, 256>>>(bufC, whi + 1 * 65536, wlo + 1 * 65536, bufB,
                                 nullptr, rc2, batch, b1, N, 0);
    // 7. agg2[dst] += v * h2_lin[src]
    scatter_kernel<<<scatterBlocks, 256>>>(bufB, bufD, src, dst, values, E);
    // 8. out = leaky( leaky(agg2 + b2) @ Wltop + rc3[batch] + bl )
    gemm_tf32<<<gemmGrid, 256>>>(bufD, whi + 3 * 65536, wlo + 3 * 65536, out,
                                 bl, rc3, batch, b2, N, 1);
}

// round 8
// speedup vs baseline: 1.9610x; 1.9610x over previous
#include <cuda_runtime.h>
#include <cuda_bf16.h>

#define NMAX 100000
#define DIM  256
#define NEG_SLOPE 0.01f

// -------------------- scratch (device globals) --------------------
__device__ float BUF_B[(size_t)NMAX * DIM];  // h_lin / h2_lin (gemm outputs)
__device__ float BUF_C[(size_t)NMAX * DIM];  // agg1
__device__ float BUF_D[(size_t)NMAX * DIM];  // agg2
__device__ float WHI[5 * 65536];             // tf32-hi of W1, W2top, W2bot, Wltop, Wlbot
__device__ float WLO[5 * 65536];             // residual lo
__device__ float RA2[128 * DIM];             // leaky(features[root])
__device__ float RA3[128 * DIM];             // h1[root] = agg1[root]+b1
__device__ float RC2[128 * DIM];             // RA2 @ W2bot
__device__ float RC3[128 * DIM];             // RA3 @ Wlbot

__device__ __forceinline__ float leaky1(float v) { return v >= 0.0f ? v : NEG_SLOPE * v; }
__device__ __forceinline__ float4 leaky4(float4 v) {
    v.x = leaky1(v.x); v.y = leaky1(v.y); v.z = leaky1(v.z); v.w = leaky1(v.w);
    return v;
}
__device__ __forceinline__ float tf32r(float x) {
    float r; asm("cvt.rna.tf32.f32 %0, %1;" : "=f"(r) : "f"(x)); return r;
}

// -------------------- weight decomposition --------------------
__global__ void decompose_w(const float* __restrict__ W1, const float* __restrict__ W2,
                            const float* __restrict__ Wl) {
    int slot = blockIdx.y;
    int idx = blockIdx.x * 256 + threadIdx.x;
    const float* src;
    if (slot == 0) src = W1;
    else if (slot == 1) src = W2;
    else if (slot == 2) src = W2 + 65536;
    else if (slot == 3) src = Wl;
    else src = Wl + 65536;
    float v = src[idx];
    float hi = tf32r(v);
    WHI[slot * 65536 + idx] = hi;
    WLO[slot * 65536 + idx] = tf32r(v - hi);
}

// -------------------- tf32 tensor-core GEMM (R4 layout) --------------------
// C[nrows,256] = op(A)[nrows,256] @ B[256,256]; op = leaky(x + abias) if abias.
// 3-pass split: Ahi*Bhi + Ahi*Blo + Alo*Bhi.
// Epilogue: +bias, +rc[batch[row]], optional leaky.
#define GAPAD 20   // As row pitch (16 + 4)
#define GBPAD 132  // Bs row pitch (128 + 4)

__device__ __forceinline__ void mma8(float* c, const float* a, const float* b) {
    asm volatile(
        "mma.sync.aligned.m16n8k8.row.col.f32.tf32.tf32.f32 "
        "{%0,%1,%2,%3}, {%4,%5,%6,%7}, {%8,%9}, {%0,%1,%2,%3};"
        : "+f"(c[0]), "+f"(c[1]), "+f"(c[2]), "+f"(c[3])
        : "r"(__float_as_uint(a[0])), "r"(__float_as_uint(a[1])),
          "r"(__float_as_uint(a[2])), "r"(__float_as_uint(a[3])),
          "r"(__float_as_uint(b[0])), "r"(__float_as_uint(b[1])));
}

__global__ void __launch_bounds__(256, 1) gemm_tf32(
    const float* __restrict__ A, const float* __restrict__ BH, const float* __restrict__ BL,
    float* __restrict__ C, const float* __restrict__ bias,
    const float* __restrict__ rc, const int* __restrict__ batch,
    const float* __restrict__ abias,
    int nrows, int leakyFlag)
{
    __shared__ float As_hi[128 * GAPAD];
    __shared__ float As_lo[128 * GAPAD];
    __shared__ float Bs_hi[16 * GBPAD];
    __shared__ float Bs_lo[16 * GBPAD];

    const int tid = threadIdx.x;
    const int warp = tid >> 5, lane = tid & 31;
    const int g = lane >> 2, t = lane & 3;
    const int wm = (warp & 1) * 64;
    const int wn = (warp >> 1) * 32;
    const int row0 = blockIdx.x * 128;
    const int col0 = blockIdx.y * 128;

    float acc[4][4][4];
    #pragma unroll
    for (int mt = 0; mt < 4; mt++)
        #pragma unroll
        for (int nt = 0; nt < 4; nt++)
            #pragma unroll
            for (int i = 0; i < 4; i++) acc[mt][nt][i] = 0.0f;

    float4 ra[2], rbh[2], rbl[2];

    // prefetch chunk 0
    #pragma unroll
    for (int i = 0; i < 2; i++) {
        int f = tid + 256 * i;
        int r = f >> 2, c4 = (f & 3) * 4;
        int gr = row0 + r;
        ra[i] = (gr < nrows) ? *(const float4*)(A + (long long)gr * 256 + c4)
                             : make_float4(0.f, 0.f, 0.f, 0.f);
        int kr = f >> 5, bc = (f & 31) * 4;
        rbh[i] = *(const float4*)(BH + (long long)kr * 256 + col0 + bc);
        rbl[i] = *(const float4*)(BL + (long long)kr * 256 + col0 + bc);
    }

    for (int ch = 0; ch < 16; ch++) {
        int k0 = ch * 16;
        __syncthreads();
        // stage into smem with fused A transform + hi/lo split
        #pragma unroll
        for (int i = 0; i < 2; i++) {
            int f = tid + 256 * i;
            int r = f >> 2, c4 = (f & 3) * 4;
            float4 v = ra[i];
            if (abias) {
                float4 ab = *(const float4*)(abias + k0 + c4);
                v.x += ab.x; v.y += ab.y; v.z += ab.z; v.w += ab.w;
                v = leaky4(v);
            }
            float hx = tf32r(v.x), hy = tf32r(v.y), hz = tf32r(v.z), hw = tf32r(v.w);
            As_hi[r * GAPAD + c4 + 0] = hx;
            As_hi[r * GAPAD + c4 + 1] = hy;
            As_hi[r * GAPAD + c4 + 2] = hz;
            As_hi[r * GAPAD + c4 + 3] = hw;
            As_lo[r * GAPAD + c4 + 0] = tf32r(v.x - hx);
            As_lo[r * GAPAD + c4 + 1] = tf32r(v.y - hy);
            As_lo[r * GAPAD + c4 + 2] = tf32r(v.z - hz);
            As_lo[r * GAPAD + c4 + 3] = tf32r(v.w - hw);
            int kr = f >> 5, bc = (f & 31) * 4;
            *(float4*)&Bs_hi[kr * GBPAD + bc] = rbh[i];
            *(float4*)&Bs_lo[kr * GBPAD + bc] = rbl[i];
        }
        __syncthreads();

        // prefetch next chunk
        if (ch < 15) {
            int kn = k0 + 16;
            #pragma unroll
            for (int i = 0; i < 2; i++) {
                int f = tid + 256 * i;
                int r = f >> 2, c4 = (f & 3) * 4;
                int gr = row0 + r;
                ra[i] = (gr < nrows) ? *(const float4*)(A + (long long)gr * 256 + kn + c4)
                                     : make_float4(0.f, 0.f, 0.f, 0.f);
                int kr = f >> 5, bc = (f & 31) * 4;
                rbh[i] = *(const float4*)(BH + (long long)(kn + kr) * 256 + col0 + bc);
                rbl[i] = *(const float4*)(BL + (long long)(kn + kr) * 256 + col0 + bc);
            }
        }

        // compute: 2 k8 substeps
        #pragma unroll
        for (int ks = 0; ks < 2; ks++) {
            int kk = ks * 8;
            float ah[4][4], al[4][4];
            #pragma unroll
            for (int mt = 0; mt < 4; mt++) {
                int base = (wm + mt * 16 + g) * GAPAD + kk + t;
                int base8 = base + 8 * GAPAD;
                ah[mt][0] = As_hi[base];     ah[mt][1] = As_hi[base8];
                ah[mt][2] = As_hi[base + 4]; ah[mt][3] = As_hi[base8 + 4];
                al[mt][0] = As_lo[base];     al[mt][1] = As_lo[base8];
                al[mt][2] = As_lo[base + 4]; al[mt][3] = As_lo[base8 + 4];
            }
            float bh[4][2], bl2[4][2];
            #pragma unroll
            for (int nt = 0; nt < 4; nt++) {
                int cb = wn + nt * 8 + g;
                bh[nt][0]  = Bs_hi[(kk + t) * GBPAD + cb];
                bh[nt][1]  = Bs_hi[(kk + t + 4) * GBPAD + cb];
                bl2[nt][0] = Bs_lo[(kk + t) * GBPAD + cb];
                bl2[nt][1] = Bs_lo[(kk + t + 4) * GBPAD + cb];
            }
            #pragma unroll
            for (int mt = 0; mt < 4; mt++)
                #pragma unroll
                for (int nt = 0; nt < 4; nt++) {
                    mma8(acc[mt][nt], ah[mt], bh[nt]);
                    mma8(acc[mt][nt], ah[mt], bl2[nt]);
                    mma8(acc[mt][nt], al[mt], bh[nt]);
                }
        }
    }

    // epilogue
    #pragma unroll
    for (int mt = 0; mt < 4; mt++) {
        int r_lo = row0 + wm + mt * 16 + g;
        #pragma unroll
        for (int h = 0; h < 2; h++) {
            int gr = r_lo + 8 * h;
            if (gr >= nrows) continue;
            const float* rcrow = rc ? rc + (long long)batch[gr] * 256 : nullptr;
            #pragma unroll
            for (int nt = 0; nt < 4; nt++) {
                int gc = col0 + wn + nt * 8 + 2 * t;
                float vx = acc[mt][nt][h * 2 + 0];
                float vy = acc[mt][nt][h * 2 + 1];
                if (bias) { float2 bb = *(const float2*)(bias + gc); vx += bb.x; vy += bb.y; }
                if (rcrow) { float2 rr = *(const float2*)(rcrow + gc); vx += rr.x; vy += rr.y; }
                if (leakyFlag) { vx = leaky1(vx); vy = leaky1(vy); }
                float2 o; o.x = vx; o.y = vy;
                *(float2*)(C + (long long)gr * 256 + gc) = o;
            }
        }
    }
}

// -------------------- tiny root GEMM (fp32 FFMA, high-parallelism) ----------
// C[nrows,256] = A[nrows,256] @ Bm[256,256], nrows <= 128.
// One block per 16-row strip; thread owns one output column across 16 rows.
__global__ void __launch_bounds__(256) tiny_gemm(
    const float* __restrict__ A, const float* __restrict__ Bm,
    float* __restrict__ C, int nrows)
{
    __shared__ float As[16][260];
    int row0 = blockIdx.x * 16;
    int col = threadIdx.x;

    for (int i = threadIdx.x; i < 16 * 256; i += 256) {
        int r = i >> 8, c = i & 255;
        As[r][c] = (row0 + r < nrows) ? A[(long long)(row0 + r) * 256 + c] : 0.f;
    }
    __syncthreads();

    float acc[16];
    #pragma unroll
    for (int r = 0; r < 16; r++) acc[r] = 0.f;

    for (int k = 0; k < 256; k += 4) {
        float b0 = Bm[(long long)(k + 0) * 256 + col];
        float b1 = Bm[(long long)(k + 1) * 256 + col];
        float b2 = Bm[(long long)(k + 2) * 256 + col];
        float b3 = Bm[(long long)(k + 3) * 256 + col];
        #pragma unroll
        for (int r = 0; r < 16; r++) {
            float4 av = *(const float4*)&As[r][k];
            acc[r] += av.x * b0 + av.y * b1 + av.z * b2 + av.w * b3;
        }
    }
    #pragma unroll
    for (int r = 0; r < 16; r++)
        if (row0 + r < nrows) C[(long long)(row0 + r) * 256 + col] = acc[r];
}

// -------------------- edge scatter: agg[dst] += w * h[src] --------------------
__global__ void __launch_bounds__(256) scatter_kernel(
    const float* __restrict__ h, float* __restrict__ agg,
    const int* __restrict__ src, const int* __restrict__ dst,
    const float* __restrict__ w, int E)
{
    int warp = (blockIdx.x * blockDim.x + threadIdx.x) >> 5;
    int lane = threadIdx.x & 31;
    if (warp >= E) return;
    int s = src[warp], d = dst[warp];
    float wt = w[warp];
    const float4* hrow = (const float4*)(h + (long long)s * DIM);
    float* arow = agg + (long long)d * DIM;
    #pragma unroll
    for (int i = 0; i < 2; i++) {
        int gidx = lane + 32 * i;
        float4 v = __ldg(hrow + gidx);
        float* p = arow + gidx * 4;
        asm volatile("red.global.add.v4.f32 [%0], {%1,%2,%3,%4};"
                     :: "l"(p), "f"(wt * v.x), "f"(wt * v.y), "f"(wt * v.z), "f"(wt * v.w)
                     : "memory");
    }
}

// -------------------- small helpers --------------------
__global__ void zero2_kernel(float4* __restrict__ p, float4* __restrict__ q, long long n4) {
    long long i = (long long)blockIdx.x * blockDim.x + threadIdx.x;
    if (i < n4) {
        p[i] = make_float4(0.f, 0.f, 0.f, 0.f);
        q[i] = make_float4(0.f, 0.f, 0.f, 0.f);
    }
}

// dst[b] = op(src[root_idx[b]]) ; op: +abias (optional), leaky (optional)
__global__ void __launch_bounds__(64) gather_root(
    const float* __restrict__ src, const int* __restrict__ root_idx,
    const float* __restrict__ abias,
    float* __restrict__ dst, int applyLeaky)
{
    int b = blockIdx.x, t = threadIdx.x;
    int r = root_idx[b];
    float4 v = ((const float4*)(src + (long long)r * DIM))[t];
    if (abias) {
        float4 ab = ((const float4*)abias)[t];
        v.x += ab.x; v.y += ab.y; v.z += ab.z; v.w += ab.w;
    }
    if (applyLeaky) v = leaky4(v);
    ((float4*)(dst + (long long)b * DIM))[t] = v;
}

// -------------------- launch --------------------
extern "C" void kernel_launch(void* const* d_in, const int* in_sizes, int n_in,
                              void* d_out, int out_size)
{
    const float* features = (const float*)d_in[0];
    const float* values   = (const float*)d_in[1];
    const float* W1       = (const float*)d_in[2];
    const float* b1       = (const float*)d_in[3];
    const float* W2       = (const float*)d_in[4];
    const float* b2       = (const float*)d_in[5];
    const float* Wl       = (const float*)d_in[6];
    const float* bl       = (const float*)d_in[7];
    const int*   adjs     = (const int*)d_in[8];
    const int*   batch    = (const int*)d_in[9];
    const int*   root_idx = (const int*)d_in[10];
    float* out = (float*)d_out;

    const int N = in_sizes[0] / DIM;
    const int E = in_sizes[1];
    const int B = in_sizes[10];
    const int* src = adjs;
    const int* dst = adjs + E;

    float *bufB, *bufC, *bufD, *whi, *wlo, *ra2, *ra3, *rc2, *rc3;
    cudaGetSymbolAddress((void**)&bufB, BUF_B);
    cudaGetSymbolAddress((void**)&bufC, BUF_C);
    cudaGetSymbolAddress((void**)&bufD, BUF_D);
    cudaGetSymbolAddress((void**)&whi, WHI);
    cudaGetSymbolAddress((void**)&wlo, WLO);
    cudaGetSymbolAddress((void**)&ra2, RA2);
    cudaGetSymbolAddress((void**)&ra3, RA3);
    cudaGetSymbolAddress((void**)&rc2, RC2);
    cudaGetSymbolAddress((void**)&rc3, RC3);

    dim3 gemmGrid((N + 127) / 128, 2);
    int tinyBlocks = (B + 15) / 16;
    int scatterBlocks = (E + 7) / 8;
    long long n4 = (long long)N * DIM / 4;
    int zeroBlocks = (int)((n4 + 255) / 256);

    // 1. decompose weights; zero both agg buffers
    decompose_w<<<dim3(256, 5), 256>>>(W1, W2, Wl);
    zero2_kernel<<<zeroBlocks, 256>>>((float4*)bufC, (float4*)bufD, n4);
    // 2. rc2 = leaky(features[root]) @ W2bot    (fp32 tiny path)
    gather_root<<<B, 64>>>(features, root_idx, nullptr, ra2, 1);
    tiny_gemm<<<tinyBlocks, 256>>>(ra2, W2 + 65536, rc2, B);
    // 3. h_lin = features @ W1
    gemm_tf32<<<gemmGrid, 256>>>(features, whi, wlo, bufB,
                                 nullptr, nullptr, nullptr, nullptr, N, 0);
    // 4. agg1[dst] += v * h_lin[src]
    scatter_kernel<<<scatterBlocks, 256>>>(bufB, bufC, src, dst, values, E);
    // 5. rc3 = (agg1[root] + b1) @ Wlbot        (fp32 tiny path)
    gather_root<<<B, 64>>>(bufC, root_idx, b1, ra3, 0);
    tiny_gemm<<<tinyBlocks, 256>>>(ra3, Wl + 65536, rc3, B);
    // 6. h2_lin = leaky(agg1 + b1) @ W2top + rc2[batch]   (A-transform fused)
    gemm_tf32<<<gemmGrid, 256>>>(bufC, whi + 1 * 65536, wlo + 1 * 65536, bufB,
                                 nullptr, rc2, batch, b1, N, 0);
    // 7. agg2[dst] += v * h2_lin[src]
    scatter_kernel<<<scatterBlocks, 256>>>(bufB, bufD, src, dst, values, E);
    // 8. out = leaky( leaky(agg2 + b2) @ Wltop + rc3[batch] + bl )
    gemm_tf32<<<gemmGrid, 256>>>(bufD, whi + 3 * 65536, wlo + 3 * 65536, out,
                                 bl, rc3, batch, b2, N, 1);
}

// round 9
// speedup vs baseline: 2.9850x; 1.5222x over previous
#include <cuda_runtime.h>
#include <cuda_bf16.h>

#define NMAX 100000
#define DIM  256
#define NEG_SLOPE 0.01f

// -------------------- scratch (device globals) --------------------
__device__ float BUF_B[(size_t)NMAX * DIM];  // h_lin / h2_lin (gemm outputs)
__device__ float BUF_C[(size_t)NMAX * DIM];  // agg1
__device__ float BUF_D[(size_t)NMAX * DIM];  // agg2
__device__ float RA2[128 * DIM];             // leaky(features[root])
__device__ float RA3[128 * DIM];             // agg1[root]+b1
__device__ float RC2[128 * DIM];             // RA2 @ W2bot
__device__ float RC3[128 * DIM];             // RA3 @ Wlbot

__device__ __forceinline__ float leaky1(float v) { return v >= 0.0f ? v : NEG_SLOPE * v; }
__device__ __forceinline__ float4 leaky4(float4 v) {
    v.x = leaky1(v.x); v.y = leaky1(v.y); v.z = leaky1(v.z); v.w = leaky1(v.w);
    return v;
}
__device__ __forceinline__ float tf32r(float x) {
    float r; asm("cvt.rna.tf32.f32 %0, %1;" : "=f"(r) : "f"(x)); return r;
}

// -------------------- tf32 tensor-core GEMM, 1-pass --------------------
// Main task : C[nrows,256]  = op(A)[nrows,256] @ B[256,256]
//             op = leaky(x + abias) if abias; epilogue +bias, +rc[batch[r]], leaky.
// Aux task  : last grid.x block computes auxC[auxRows,256] = auxA @ auxB (plain).
#define GAPAD 20   // As row pitch (16 + 4)
#define GBPAD 132  // Bs row pitch (128 + 4)

__device__ __forceinline__ void mma8(float* c, const float* a, const float* b) {
    asm volatile(
        "mma.sync.aligned.m16n8k8.row.col.f32.tf32.tf32.f32 "
        "{%0,%1,%2,%3}, {%4,%5,%6,%7}, {%8,%9}, {%0,%1,%2,%3};"
        : "+f"(c[0]), "+f"(c[1]), "+f"(c[2]), "+f"(c[3])
        : "r"(__float_as_uint(a[0])), "r"(__float_as_uint(a[1])),
          "r"(__float_as_uint(a[2])), "r"(__float_as_uint(a[3])),
          "r"(__float_as_uint(b[0])), "r"(__float_as_uint(b[1])));
}

__global__ void __launch_bounds__(256) gemm_tf32(
    const float* __restrict__ A, const float* __restrict__ Bmat,
    float* __restrict__ C, const float* __restrict__ bias,
    const float* __restrict__ rc, const int* __restrict__ batch,
    const float* __restrict__ abias, int nrows, int leakyFlag,
    const float* __restrict__ auxA, const float* __restrict__ auxB,
    float* __restrict__ auxC, int auxRows)
{
    __shared__ float As[128 * GAPAD];
    __shared__ float Bs[16 * GBPAD];

    int row0;
    if (auxA && blockIdx.x == gridDim.x - 1) {
        // aux (tiny root) task
        A = auxA; Bmat = auxB; C = auxC; nrows = auxRows;
        bias = nullptr; rc = nullptr; abias = nullptr; leakyFlag = 0;
        row0 = 0;
    } else {
        row0 = blockIdx.x * 128;
    }
    const int col0 = blockIdx.y * 128;

    const int tid = threadIdx.x;
    const int warp = tid >> 5, lane = tid & 31;
    const int g = lane >> 2, t = lane & 3;
    const int wm = (warp & 1) * 64;
    const int wn = (warp >> 1) * 32;

    float acc[4][4][4];
    #pragma unroll
    for (int mt = 0; mt < 4; mt++)
        #pragma unroll
        for (int nt = 0; nt < 4; nt++)
            #pragma unroll
            for (int i = 0; i < 4; i++) acc[mt][nt][i] = 0.0f;

    float4 ra[2], rb[2];

    // prefetch chunk 0
    #pragma unroll
    for (int i = 0; i < 2; i++) {
        int f = tid + 256 * i;
        int r = f >> 2, c4 = (f & 3) * 4;
        int gr = row0 + r;
        ra[i] = (gr < nrows) ? *(const float4*)(A + (long long)gr * 256 + c4)
                             : make_float4(0.f, 0.f, 0.f, 0.f);
        int kr = f >> 5, bc = (f & 31) * 4;
        rb[i] = *(const float4*)(Bmat + (long long)kr * 256 + col0 + bc);
    }

    for (int ch = 0; ch < 16; ch++) {
        int k0 = ch * 16;
        __syncthreads();
        // stage: fused A transform + tf32 round; B tf32 round
        #pragma unroll
        for (int i = 0; i < 2; i++) {
            int f = tid + 256 * i;
            int r = f >> 2, c4 = (f & 3) * 4;
            float4 v = ra[i];
            if (abias) {
                float4 ab = *(const float4*)(abias + k0 + c4);
                v.x += ab.x; v.y += ab.y; v.z += ab.z; v.w += ab.w;
                v = leaky4(v);
            }
            As[r * GAPAD + c4 + 0] = tf32r(v.x);
            As[r * GAPAD + c4 + 1] = tf32r(v.y);
            As[r * GAPAD + c4 + 2] = tf32r(v.z);
            As[r * GAPAD + c4 + 3] = tf32r(v.w);
            int kr = f >> 5, bc = (f & 31) * 4;
            float4 w = rb[i];
            Bs[kr * GBPAD + bc + 0] = tf32r(w.x);
            Bs[kr * GBPAD + bc + 1] = tf32r(w.y);
            Bs[kr * GBPAD + bc + 2] = tf32r(w.z);
            Bs[kr * GBPAD + bc + 3] = tf32r(w.w);
        }
        __syncthreads();

        // prefetch next chunk
        if (ch < 15) {
            int kn = k0 + 16;
            #pragma unroll
            for (int i = 0; i < 2; i++) {
                int f = tid + 256 * i;
                int r = f >> 2, c4 = (f & 3) * 4;
                int gr = row0 + r;
                ra[i] = (gr < nrows) ? *(const float4*)(A + (long long)gr * 256 + kn + c4)
                                     : make_float4(0.f, 0.f, 0.f, 0.f);
                int kr = f >> 5, bc = (f & 31) * 4;
                rb[i] = *(const float4*)(Bmat + (long long)(kn + kr) * 256 + col0 + bc);
            }
        }

        // compute: 2 k8 substeps, 16 MMAs each
        #pragma unroll
        for (int ks = 0; ks < 2; ks++) {
            int kk = ks * 8;
            float ah[4][4];
            #pragma unroll
            for (int mt = 0; mt < 4; mt++) {
                int base = (wm + mt * 16 + g) * GAPAD + kk + t;
                int base8 = base + 8 * GAPAD;
                ah[mt][0] = As[base];     ah[mt][1] = As[base8];
                ah[mt][2] = As[base + 4]; ah[mt][3] = As[base8 + 4];
            }
            float bh[4][2];
            #pragma unroll
            for (int nt = 0; nt < 4; nt++) {
                int cb = wn + nt * 8 + g;
                bh[nt][0] = Bs[(kk + t) * GBPAD + cb];
                bh[nt][1] = Bs[(kk + t + 4) * GBPAD + cb];
            }
            #pragma unroll
            for (int mt = 0; mt < 4; mt++)
                #pragma unroll
                for (int nt = 0; nt < 4; nt++)
                    mma8(acc[mt][nt], ah[mt], bh[nt]);
        }
    }

    // epilogue
    #pragma unroll
    for (int mt = 0; mt < 4; mt++) {
        int r_lo = row0 + wm + mt * 16 + g;
        #pragma unroll
        for (int h = 0; h < 2; h++) {
            int gr = r_lo + 8 * h;
            if (gr >= nrows) continue;
            const float* rcrow = rc ? rc + (long long)batch[gr] * 256 : nullptr;
            #pragma unroll
            for (int nt = 0; nt < 4; nt++) {
                int gc = col0 + wn + nt * 8 + 2 * t;
                float vx = acc[mt][nt][h * 2 + 0];
                float vy = acc[mt][nt][h * 2 + 1];
                if (bias) { float2 bb = *(const float2*)(bias + gc); vx += bb.x; vy += bb.y; }
                if (rcrow) { float2 rr = *(const float2*)(rcrow + gc); vx += rr.x; vy += rr.y; }
                if (leakyFlag) { vx = leaky1(vx); vy = leaky1(vy); }
                float2 o; o.x = vx; o.y = vy;
                *(float2*)(C + (long long)gr * 256 + gc) = o;
            }
        }
    }
}

// -------------------- edge scatter: agg[dst] += w * h[src] --------------------
__global__ void __launch_bounds__(256) scatter_kernel(
    const float* __restrict__ h, float* __restrict__ agg,
    const int* __restrict__ src, const int* __restrict__ dst,
    const float* __restrict__ w, int E)
{
    int warp = (blockIdx.x * blockDim.x + threadIdx.x) >> 5;
    int lane = threadIdx.x & 31;
    if (warp >= E) return;
    int s = src[warp], d = dst[warp];
    float wt = w[warp];
    const float4* hrow = (const float4*)(h + (long long)s * DIM);
    float* arow = agg + (long long)d * DIM;
    #pragma unroll
    for (int i = 0; i < 2; i++) {
        int gidx = lane + 32 * i;
        float4 v = __ldg(hrow + gidx);
        float* p = arow + gidx * 4;
        asm volatile("red.global.add.v4.f32 [%0], {%1,%2,%3,%4};"
                     :: "l"(p), "f"(wt * v.x), "f"(wt * v.y), "f"(wt * v.z), "f"(wt * v.w)
                     : "memory");
    }
}

// -------------------- small helpers --------------------
__global__ void zero2_kernel(float4* __restrict__ p, float4* __restrict__ q, long long n4) {
    long long i = (long long)blockIdx.x * blockDim.x + threadIdx.x;
    if (i < n4) {
        p[i] = make_float4(0.f, 0.f, 0.f, 0.f);
        q[i] = make_float4(0.f, 0.f, 0.f, 0.f);
    }
}

// dst[b] = op(src[root_idx[b]]) ; op: +abias (optional), leaky (optional)
__global__ void __launch_bounds__(64) gather_root(
    const float* __restrict__ src, const int* __restrict__ root_idx,
    const float* __restrict__ abias,
    float* __restrict__ dst, int applyLeaky)
{
    int b = blockIdx.x, t = threadIdx.x;
    int r = root_idx[b];
    float4 v = ((const float4*)(src + (long long)r * DIM))[t];
    if (abias) {
        float4 ab = ((const float4*)abias)[t];
        v.x += ab.x; v.y += ab.y; v.z += ab.z; v.w += ab.w;
    }
    if (applyLeaky) v = leaky4(v);
    ((float4*)(dst + (long long)b * DIM))[t] = v;
}

// -------------------- launch --------------------
extern "C" void kernel_launch(void* const* d_in, const int* in_sizes, int n_in,
                              void* d_out, int out_size)
{
    const float* features = (const float*)d_in[0];
    const float* values   = (const float*)d_in[1];
    const float* W1       = (const float*)d_in[2];
    const float* b1       = (const float*)d_in[3];
    const float* W2       = (const float*)d_in[4];
    const float* b2       = (const float*)d_in[5];
    const float* Wl       = (const float*)d_in[6];
    const float* bl       = (const float*)d_in[7];
    const int*   adjs     = (const int*)d_in[8];
    const int*   batch    = (const int*)d_in[9];
    const int*   root_idx = (const int*)d_in[10];
    float* out = (float*)d_out;

    const int N = in_sizes[0] / DIM;
    const int E = in_sizes[1];
    const int B = in_sizes[10];
    const int* src = adjs;
    const int* dst = adjs + E;

    float *bufB, *bufC, *bufD, *ra2, *ra3, *rc2, *rc3;
    cudaGetSymbolAddress((void**)&bufB, BUF_B);
    cudaGetSymbolAddress((void**)&bufC, BUF_C);
    cudaGetSymbolAddress((void**)&bufD, BUF_D);
    cudaGetSymbolAddress((void**)&ra2, RA2);
    cudaGetSymbolAddress((void**)&ra3, RA3);
    cudaGetSymbolAddress((void**)&rc2, RC2);
    cudaGetSymbolAddress((void**)&rc3, RC3);

    int mainBlocks = (N + 127) / 128;
    dim3 gridAux(mainBlocks + 1, 2);    // +1 block for fused tiny root GEMM
    dim3 gridMain(mainBlocks, 2);
    int scatterBlocks = (E + 7) / 8;
    long long n4 = (long long)N * DIM / 4;
    int zeroBlocks = (int)((n4 + 255) / 256);

    // 1. zero both agg buffers; gather leaky(features[root])
    zero2_kernel<<<zeroBlocks, 256>>>((float4*)bufC, (float4*)bufD, n4);
    gather_root<<<B, 64>>>(features, root_idx, nullptr, ra2, 1);
    // 2. h_lin = features @ W1  [+ aux: rc2 = RA2 @ W2bot]
    gemm_tf32<<<gridAux, 256>>>(features, W1, bufB,
                                nullptr, nullptr, nullptr, nullptr, N, 0,
                                ra2, W2 + 65536, rc2, B);
    // 3. agg1[dst] += v * h_lin[src]
    scatter_kernel<<<scatterBlocks, 256>>>(bufB, bufC, src, dst, values, E);
    // 4. ra3 = agg1[root] + b1
    gather_root<<<B, 64>>>(bufC, root_idx, b1, ra3, 0);
    // 5. h2_lin = leaky(agg1+b1) @ W2top + rc2[batch]  [+ aux: rc3 = RA3 @ Wlbot]
    gemm_tf32<<<gridAux, 256>>>(bufC, W2, bufB,
                                nullptr, rc2, batch, b1, N, 0,
                                ra3, Wl + 65536, rc3, B);
    // 6. agg2[dst] += v * h2_lin[src]
    scatter_kernel<<<scatterBlocks, 256>>>(bufB, bufD, src, dst, values, E);
    // 7. out = leaky( leaky(agg2+b2) @ Wltop + rc3[batch] + bl )
    gemm_tf32<<<gridMain, 256>>>(bufD, Wl, out,
                                 bl, rc3, batch, b2, N, 1,
                                 nullptr, nullptr, nullptr, 0);
}

// round 10
// speedup vs baseline: 3.7209x; 1.2465x over previous
#include <cuda_runtime.h>
#include <cuda_bf16.h>

#define NMAX 100000
#define DIM  256
#define NEG_SLOPE 0.01f

// -------------------- scratch (device globals) --------------------
__device__ float BUF_B[(size_t)NMAX * DIM];  // h_lin / h2_lin (gemm outputs)
__device__ float BUF_C[(size_t)NMAX * DIM];  // agg1
__device__ float BUF_D[(size_t)NMAX * DIM];  // agg2
__device__ float RA2[128 * DIM];             // leaky(features[root])
__device__ float RA3[128 * DIM];             // agg1[root]+b1
__device__ float RC2[128 * DIM];             // RA2 @ W2bot
__device__ float RC3[128 * DIM];             // RA3 @ Wlbot

__device__ __forceinline__ float leaky1(float v) { return v >= 0.0f ? v : NEG_SLOPE * v; }
__device__ __forceinline__ float4 leaky4(float4 v) {
    v.x = leaky1(v.x); v.y = leaky1(v.y); v.z = leaky1(v.z); v.w = leaky1(v.w);
    return v;
}
__device__ __forceinline__ float tf32r(float x) {
    float r; asm("cvt.rna.tf32.f32 %0, %1;" : "=f"(r) : "f"(x)); return r;
}

// -------------------- tf32 tensor-core GEMM, 1-pass, 64x128 tile ------------
// Main : C[nrows,256] = op(A)[nrows,256] @ B[256,256]
//        op = leaky(x + abias) if abias; epilogue +bias, +rc[batch[r]], leaky.
// Aux  : last 2 grid.x blocks compute auxC[auxRows,256] = auxA @ auxB (plain).
// 256 threads = 8 warps (2m x 4n), warp tile 32x32, double-buffered K chunks.
#define GAPAD 20   // As row pitch (16 + 4)
#define GBPAD 132  // Bs row pitch (128 + 4)

__device__ __forceinline__ void mma8(float* c, const float* a, const float* b) {
    asm volatile(
        "mma.sync.aligned.m16n8k8.row.col.f32.tf32.tf32.f32 "
        "{%0,%1,%2,%3}, {%4,%5,%6,%7}, {%8,%9}, {%0,%1,%2,%3};"
        : "+f"(c[0]), "+f"(c[1]), "+f"(c[2]), "+f"(c[3])
        : "r"(__float_as_uint(a[0])), "r"(__float_as_uint(a[1])),
          "r"(__float_as_uint(a[2])), "r"(__float_as_uint(a[3])),
          "r"(__float_as_uint(b[0])), "r"(__float_as_uint(b[1])));
}

__global__ void __launch_bounds__(256, 3) gemm_tf32(
    const float* __restrict__ A, const float* __restrict__ Bmat,
    float* __restrict__ C, const float* __restrict__ bias,
    const float* __restrict__ rc, const int* __restrict__ batch,
    const float* __restrict__ abias, int nrows, int leakyFlag,
    const float* __restrict__ auxA, const float* __restrict__ auxB,
    float* __restrict__ auxC, int auxRows)
{
    __shared__ float As[2][64 * GAPAD];
    __shared__ float Bs[2][16 * GBPAD];

    int row0;
    {
        int mainBlocks = gridDim.x - (auxA ? 2 : 0);
        if (auxA && (int)blockIdx.x >= mainBlocks) {
            A = auxA; Bmat = auxB; C = auxC;
            nrows = auxRows;
            bias = nullptr; rc = nullptr; abias = nullptr; leakyFlag = 0;
            row0 = (blockIdx.x - mainBlocks) * 64;
        } else {
            row0 = blockIdx.x * 64;
        }
    }
    const int col0 = blockIdx.y * 128;

    const int tid = threadIdx.x;
    const int warp = tid >> 5, lane = tid & 31;
    const int g = lane >> 2, t = lane & 3;
    const int wm = (warp & 1) * 32;        // 0 / 32
    const int wn = (warp >> 1) * 32;       // 0,32,64,96

    float acc[2][4][4];
    #pragma unroll
    for (int mt = 0; mt < 2; mt++)
        #pragma unroll
        for (int nt = 0; nt < 4; nt++)
            #pragma unroll
            for (int i = 0; i < 4; i++) acc[mt][nt][i] = 0.0f;

    // staging thread coordinates
    const int ar  = tid >> 2;          // A row 0..63
    const int ac4 = (tid & 3) * 4;     // A k-col group
    const int kr0 = tid >> 5;          // B k-row 0..7
    const int kr1 = kr0 + 8;           // B k-row 8..15
    const int bc  = (tid & 31) * 4;    // B col group

    float4 ra, rb0, rb1;
    {
        int gr = row0 + ar;
        ra  = (gr < nrows) ? *(const float4*)(A + (long long)gr * 256 + ac4)
                           : make_float4(0.f, 0.f, 0.f, 0.f);
        rb0 = *(const float4*)(Bmat + (long long)kr0 * 256 + col0 + bc);
        rb1 = *(const float4*)(Bmat + (long long)kr1 * 256 + col0 + bc);
    }

    for (int ch = 0; ch < 16; ch++) {
        const int s = ch & 1;
        // ---- store current chunk into stage s (fused A transform + tf32) ----
        {
            float4 v = ra;
            if (abias) {
                float4 ab = *(const float4*)(abias + ch * 16 + ac4);
                v.x += ab.x; v.y += ab.y; v.z += ab.z; v.w += ab.w;
                v = leaky4(v);
            }
            float* ap = &As[s][ar * GAPAD + ac4];
            ap[0] = tf32r(v.x); ap[1] = tf32r(v.y);
            ap[2] = tf32r(v.z); ap[3] = tf32r(v.w);
            float4 w0, w1;
            w0.x = tf32r(rb0.x); w0.y = tf32r(rb0.y); w0.z = tf32r(rb0.z); w0.w = tf32r(rb0.w);
            w1.x = tf32r(rb1.x); w1.y = tf32r(rb1.y); w1.z = tf32r(rb1.z); w1.w = tf32r(rb1.w);
            *(float4*)&Bs[s][kr0 * GBPAD + bc] = w0;
            *(float4*)&Bs[s][kr1 * GBPAD + bc] = w1;
        }
        // ---- prefetch next chunk (latency hidden under barrier + compute) ----
        if (ch < 15) {
            int kn = ch * 16 + 16;
            int gr = row0 + ar;
            ra  = (gr < nrows) ? *(const float4*)(A + (long long)gr * 256 + kn + ac4)
                               : make_float4(0.f, 0.f, 0.f, 0.f);
            rb0 = *(const float4*)(Bmat + (long long)(kn + kr0) * 256 + col0 + bc);
            rb1 = *(const float4*)(Bmat + (long long)(kn + kr1) * 256 + col0 + bc);
        }
        __syncthreads();

        // ---- compute from stage s: 2 k8 substeps ----
        #pragma unroll
        for (int ks = 0; ks < 2; ks++) {
            int kk = ks * 8;
            float ah[2][4];
            #pragma unroll
            for (int mt = 0; mt < 2; mt++) {
                int base  = (wm + mt * 16 + g) * GAPAD + kk + t;
                int base8 = base + 8 * GAPAD;
                ah[mt][0] = As[s][base];     ah[mt][1] = As[s][base8];
                ah[mt][2] = As[s][base + 4]; ah[mt][3] = As[s][base8 + 4];
            }
            float bh[4][2];
            #pragma unroll
            for (int nt = 0; nt < 4; nt++) {
                int cb = wn + nt * 8 + g;
                bh[nt][0] = Bs[s][(kk + t) * GBPAD + cb];
                bh[nt][1] = Bs[s][(kk + t + 4) * GBPAD + cb];
            }
            #pragma unroll
            for (int mt = 0; mt < 2; mt++)
                #pragma unroll
                for (int nt = 0; nt < 4; nt++)
                    mma8(acc[mt][nt], ah[mt], bh[nt]);
        }
    }

    // ---- epilogue ----
    #pragma unroll
    for (int mt = 0; mt < 2; mt++) {
        int r_lo = row0 + wm + mt * 16 + g;
        #pragma unroll
        for (int h = 0; h < 2; h++) {
            int gr = r_lo + 8 * h;
            if (gr >= nrows) continue;
            const float* rcrow = rc ? rc + (long long)batch[gr] * 256 : nullptr;
            #pragma unroll
            for (int nt = 0; nt < 4; nt++) {
                int gc = col0 + wn + nt * 8 + 2 * t;
                float vx = acc[mt][nt][h * 2 + 0];
                float vy = acc[mt][nt][h * 2 + 1];
                if (bias) { float2 bb = *(const float2*)(bias + gc); vx += bb.x; vy += bb.y; }
                if (rcrow) { float2 rr = *(const float2*)(rcrow + gc); vx += rr.x; vy += rr.y; }
                if (leakyFlag) { vx = leaky1(vx); vy = leaky1(vy); }
                float2 o; o.x = vx; o.y = vy;
                *(float2*)(C + (long long)gr * 256 + gc) = o;
            }
        }
    }
}

// -------------------- edge scatter: agg[dst] += w * h[src] --------------------
__global__ void __launch_bounds__(256) scatter_kernel(
    const float* __restrict__ h, float* __restrict__ agg,
    const int* __restrict__ src, const int* __restrict__ dst,
    const float* __restrict__ w, int E)
{
    int warp = (blockIdx.x * blockDim.x + threadIdx.x) >> 5;
    int lane = threadIdx.x & 31;
    if (warp >= E) return;
    int s = src[warp], d = dst[warp];
    float wt = w[warp];
    const float4* hrow = (const float4*)(h + (long long)s * DIM);
    float* arow = agg + (long long)d * DIM;
    #pragma unroll
    for (int i = 0; i < 2; i++) {
        int gidx = lane + 32 * i;
        float4 v = __ldg(hrow + gidx);
        float* p = arow + gidx * 4;
        asm volatile("red.global.add.v4.f32 [%0], {%1,%2,%3,%4};"
                     :: "l"(p), "f"(wt * v.x), "f"(wt * v.y), "f"(wt * v.z), "f"(wt * v.w)
                     : "memory");
    }
}

// -------------------- small helpers --------------------
__global__ void zero2_kernel(float4* __restrict__ p, float4* __restrict__ q, long long n4) {
    long long i = (long long)blockIdx.x * blockDim.x + threadIdx.x;
    if (i < n4) {
        p[i] = make_float4(0.f, 0.f, 0.f, 0.f);
        q[i] = make_float4(0.f, 0.f, 0.f, 0.f);
    }
}

// dst[b] = op(src[root_idx[b]]) ; op: +abias (optional), leaky (optional)
__global__ void __launch_bounds__(64) gather_root(
    const float* __restrict__ src, const int* __restrict__ root_idx,
    const float* __restrict__ abias,
    float* __restrict__ dst, int applyLeaky)
{
    int b = blockIdx.x, t = threadIdx.x;
    int r = root_idx[b];
    float4 v = ((const float4*)(src + (long long)r * DIM))[t];
    if (abias) {
        float4 ab = ((const float4*)abias)[t];
        v.x += ab.x; v.y += ab.y; v.z += ab.z; v.w += ab.w;
    }
    if (applyLeaky) v = leaky4(v);
    ((float4*)(dst + (long long)b * DIM))[t] = v;
}

// -------------------- launch --------------------
extern "C" void kernel_launch(void* const* d_in, const int* in_sizes, int n_in,
                              void* d_out, int out_size)
{
    const float* features = (const float*)d_in[0];
    const float* values   = (const float*)d_in[1];
    const float* W1       = (const float*)d_in[2];
    const float* b1       = (const float*)d_in[3];
    const float* W2       = (const float*)d_in[4];
    const float* b2       = (const float*)d_in[5];
    const float* Wl       = (const float*)d_in[6];
    const float* bl       = (const float*)d_in[7];
    const int*   adjs     = (const int*)d_in[8];
    const int*   batch    = (const int*)d_in[9];
    const int*   root_idx = (const int*)d_in[10];
    float* out = (float*)d_out;

    const int N = in_sizes[0] / DIM;
    const int E = in_sizes[1];
    const int B = in_sizes[10];
    const int* src = adjs;
    const int* dst = adjs + E;

    float *bufB, *bufC, *bufD, *ra2, *ra3, *rc2, *rc3;
    cudaGetSymbolAddress((void**)&bufB, BUF_B);
    cudaGetSymbolAddress((void**)&bufC, BUF_C);
    cudaGetSymbolAddress((void**)&bufD, BUF_D);
    cudaGetSymbolAddress((void**)&ra2, RA2);
    cudaGetSymbolAddress((void**)&ra3, RA3);
    cudaGetSymbolAddress((void**)&rc2, RC2);
    cudaGetSymbolAddress((void**)&rc3, RC3);

    int mainBlocks = (N + 63) / 64;
    dim3 gridAux(mainBlocks + 2, 2);    // +2 blocks for fused tiny root GEMM
    dim3 gridMain(mainBlocks, 2);
    int scatterBlocks = (E + 7) / 8;
    long long n4 = (long long)N * DIM / 4;
    int zeroBlocks = (int)((n4 + 255) / 256);

    // 1. zero both agg buffers; gather leaky(features[root])
    zero2_kernel<<<zeroBlocks, 256>>>((float4*)bufC, (float4*)bufD, n4);
    gather_root<<<B, 64>>>(features, root_idx, nullptr, ra2, 1);
    // 2. h_lin = features @ W1  [+ aux: rc2 = RA2 @ W2bot]
    gemm_tf32<<<gridAux, 256>>>(features, W1, bufB,
                                nullptr, nullptr, nullptr, nullptr, N, 0,
                                ra2, W2 + 65536, rc2, B);
    // 3. agg1[dst] += v * h_lin[src]
    scatter_kernel<<<scatterBlocks, 256>>>(bufB, bufC, src, dst, values, E);
    // 4. ra3 = agg1[root] + b1
    gather_root<<<B, 64>>>(bufC, root_idx, b1, ra3, 0);
    // 5. h2_lin = leaky(agg1+b1) @ W2top + rc2[batch]  [+ aux: rc3 = RA3 @ Wlbot]
    gemm_tf32<<<gridAux, 256>>>(bufC, W2, bufB,
                                nullptr, rc2, batch, b1, N, 0,
                                ra3, Wl + 65536, rc3, B);
    // 6. agg2[dst] += v * h2_lin[src]
    scatter_kernel<<<scatterBlocks, 256>>>(bufB, bufD, src, dst, values, E);
    // 7. out = leaky( leaky(agg2+b2) @ Wltop + rc3[batch] + bl )
    gemm_tf32<<<gridMain, 256>>>(bufD, Wl, out,
                                 bl, rc3, batch, b2, N, 1,
                                 nullptr, nullptr, nullptr, 0);
}